// round 4
// baseline (speedup 1.0000x reference)
#include <cuda_runtime.h>
#include <cuda_bf16.h>

// SuctionNet: out[0..n)   = w0 . feats[idx[p]] + b0   (seal)
//             out[n..2n)  = w1 . feats[idx[p]] + b1   (wrench)
// feats: [150000, 256] f32, idx: [200000] int32, w: [2,256] f32, b: [2] f32
//
// Warp owns 32 consecutive points: 1 coalesced idx load, then 4 points per
// iteration (8 independent LDG.128 in flight), 6-shuffle dual reduction
// (lanes<16 reduce seal, lanes>=16 reduce wrench).

#define FEAT_DIM 256
#define FULL 0xFFFFFFFFu

__global__ __launch_bounds__(256)
void suction_kernel(const float* __restrict__ feats,
                    const int* __restrict__ idx,
                    const float* __restrict__ w,
                    const float* __restrict__ bias,
                    float* __restrict__ out,
                    int n)
{
    const int lane = threadIdx.x & 31;
    const int warp = (blockIdx.x * blockDim.x + threadIdx.x) >> 5;
    const int base = warp * 32;
    if (base >= n) return;

    // Per-lane weight slice: 8 channels for each of the 2 scoring rows.
    const float4* w0p = reinterpret_cast<const float4*>(w) + lane * 2;
    const float4* w1p = reinterpret_cast<const float4*>(w + FEAT_DIM) + lane * 2;
    const float4 w0a = __ldg(w0p);
    const float4 w0b = __ldg(w0p + 1);
    const float4 w1a = __ldg(w1p);
    const float4 w1b = __ldg(w1p + 1);
    // Lane-selected bias for the folded reduction (lane 0 -> b0, lane 16 -> b1).
    const float bsel = (lane < 16) ? __ldg(bias) : __ldg(bias + 1);

    // One coalesced load grabs this warp's 32 indices.
    int myidx = 0;
    if (base + lane < n) myidx = __ldg(idx + base + lane);

    #pragma unroll
    for (int j0 = 0; j0 < 32; j0 += 4) {
        const int r0 = __shfl_sync(FULL, myidx, j0 + 0);
        const int r1 = __shfl_sync(FULL, myidx, j0 + 1);
        const int r2 = __shfl_sync(FULL, myidx, j0 + 2);
        const int r3 = __shfl_sync(FULL, myidx, j0 + 3);

        const float4* p0 = reinterpret_cast<const float4*>(feats + (size_t)r0 * FEAT_DIM) + lane * 2;
        const float4* p1 = reinterpret_cast<const float4*>(feats + (size_t)r1 * FEAT_DIM) + lane * 2;
        const float4* p2 = reinterpret_cast<const float4*>(feats + (size_t)r2 * FEAT_DIM) + lane * 2;
        const float4* p3 = reinterpret_cast<const float4*>(feats + (size_t)r3 * FEAT_DIM) + lane * 2;

        // 8 independent 16B loads in flight per lane.
        const float4 a0 = __ldg(p0), c0 = __ldg(p0 + 1);
        const float4 a1 = __ldg(p1), c1 = __ldg(p1 + 1);
        const float4 a2 = __ldg(p2), c2 = __ldg(p2 + 1);
        const float4 a3 = __ldg(p3), c3 = __ldg(p3 + 1);

        #pragma unroll
        for (int j = 0; j < 4; j++) {
            const float4 fa = (j == 0) ? a0 : (j == 1) ? a1 : (j == 2) ? a2 : a3;
            const float4 fb = (j == 0) ? c0 : (j == 1) ? c1 : (j == 2) ? c2 : c3;

            float s0 = fa.x * w0a.x;
            s0 = fmaf(fa.y, w0a.y, s0);
            s0 = fmaf(fa.z, w0a.z, s0);
            s0 = fmaf(fa.w, w0a.w, s0);
            s0 = fmaf(fb.x, w0b.x, s0);
            s0 = fmaf(fb.y, w0b.y, s0);
            s0 = fmaf(fb.z, w0b.z, s0);
            s0 = fmaf(fb.w, w0b.w, s0);

            float s1 = fa.x * w1a.x;
            s1 = fmaf(fa.y, w1a.y, s1);
            s1 = fmaf(fa.z, w1a.z, s1);
            s1 = fmaf(fa.w, w1a.w, s1);
            s1 = fmaf(fb.x, w1b.x, s1);
            s1 = fmaf(fb.y, w1b.y, s1);
            s1 = fmaf(fb.z, w1b.z, s1);
            s1 = fmaf(fb.w, w1b.w, s1);

            // Fold: lanes<16 carry seal partials, lanes>=16 carry wrench partials.
            const float t0 = __shfl_xor_sync(FULL, s0, 16);
            const float t1 = __shfl_xor_sync(FULL, s1, 16);
            float v = (lane < 16) ? (s0 + t0) : (s1 + t1);
            #pragma unroll
            for (int off = 8; off > 0; off >>= 1)
                v += __shfl_xor_sync(FULL, v, off);
            // lane 0 holds seal total, lane 16 holds wrench total.

            const int p = base + j0 + j;
            if (p < n) {
                if (lane == 0)  out[p]     = v + bsel;
                if (lane == 16) out[n + p] = v + bsel;
            }
        }
    }
}

extern "C" void kernel_launch(void* const* d_in, const int* in_sizes, int n_in,
                              void* d_out, int out_size)
{
    const float* feats = (const float*)d_in[0];      // [150000*256]
    const int*   idx   = (const int*)d_in[1];        // [200000] int32
    const float* w     = (const float*)d_in[2];      // [2*256]
    const float* b     = (const float*)d_in[3];      // [2]
    float* out = (float*)d_out;                      // [2 * n]

    const int n = in_sizes[1];                       // 200000 points

    const int threads = 256;                         // 8 warps/block
    const int warps_needed = (n + 31) / 32;          // 6250
    const int blocks = (warps_needed + 7) / 8;       // 782
    suction_kernel<<<blocks, threads>>>(feats, idx, w, b, out, n);
}

// round 7
// speedup vs baseline: 1.0840x; 1.0840x over previous
#include <cuda_runtime.h>
#include <cuda_bf16.h>

// SuctionNet: out[0..n)   = w0 . feats[idx[p]] + b0   (seal)
//             out[n..2n)  = w1 . feats[idx[p]] + b1   (wrench)
// feats: [150000, 256] f32, idx: [200000] int32, w: [2,256] f32, b: [2] f32
//
// Warp per point, COALESCED mapping: lane l owns channels [4l,4l+4) and
// [128+4l,128+4l+4)  -> each LDG.128 instruction covers a contiguous 512B
// (4 lines, 4 wavefronts). 8 wavefronts/point instead of 16.
// Warp batches its 32 indices in one load; folded 6-shuffle dual reduction.

#define FEAT_DIM 256
#define FULL 0xFFFFFFFFu

__global__ __launch_bounds__(128)
void suction_kernel(const float* __restrict__ feats,
                    const int* __restrict__ idx,
                    const float* __restrict__ w,
                    const float* __restrict__ bias,
                    float* __restrict__ out,
                    int n)
{
    const int lane = threadIdx.x & 31;
    const int warp = (blockIdx.x * blockDim.x + threadIdx.x) >> 5;
    const int base = warp * 32;
    if (base >= n) return;

    // Weight slices matching the coalesced row mapping.
    const float4* w0f = reinterpret_cast<const float4*>(w);
    const float4* w1f = reinterpret_cast<const float4*>(w + FEAT_DIM);
    const float4 w0a = __ldg(w0f + lane);        // channels 4l..4l+3
    const float4 w0b = __ldg(w0f + 32 + lane);   // channels 128+4l..
    const float4 w1a = __ldg(w1f + lane);
    const float4 w1b = __ldg(w1f + 32 + lane);
    const float bsel = (lane < 16) ? __ldg(bias) : __ldg(bias + 1);

    // One coalesced load grabs this warp's 32 indices (clamped, branch-free).
    const int ii = base + lane;
    const int myidx = __ldg(idx + (ii < n ? ii : n - 1));

    #pragma unroll
    for (int j0 = 0; j0 < 32; j0 += 2) {
        const int r0 = __shfl_sync(FULL, myidx, j0);
        const int r1 = __shfl_sync(FULL, myidx, j0 + 1);

        const float4* row0 = reinterpret_cast<const float4*>(feats + (size_t)r0 * FEAT_DIM);
        const float4* row1 = reinterpret_cast<const float4*>(feats + (size_t)r1 * FEAT_DIM);

        // 4 independent, fully coalesced LDG.128 (each = contiguous 512B).
        const float4 a0 = __ldg(row0 + lane);
        const float4 b0 = __ldg(row0 + 32 + lane);
        const float4 a1 = __ldg(row1 + lane);
        const float4 b1 = __ldg(row1 + 32 + lane);

        #pragma unroll
        for (int j = 0; j < 2; j++) {
            const float4 fa = j ? a1 : a0;
            const float4 fb = j ? b1 : b0;

            float s0 = fa.x * w0a.x;
            s0 = fmaf(fa.y, w0a.y, s0);
            s0 = fmaf(fa.z, w0a.z, s0);
            s0 = fmaf(fa.w, w0a.w, s0);
            s0 = fmaf(fb.x, w0b.x, s0);
            s0 = fmaf(fb.y, w0b.y, s0);
            s0 = fmaf(fb.z, w0b.z, s0);
            s0 = fmaf(fb.w, w0b.w, s0);

            float s1 = fa.x * w1a.x;
            s1 = fmaf(fa.y, w1a.y, s1);
            s1 = fmaf(fa.z, w1a.z, s1);
            s1 = fmaf(fa.w, w1a.w, s1);
            s1 = fmaf(fb.x, w1b.x, s1);
            s1 = fmaf(fb.y, w1b.y, s1);
            s1 = fmaf(fb.z, w1b.z, s1);
            s1 = fmaf(fb.w, w1b.w, s1);

            // Fold: lanes<16 carry seal partials, lanes>=16 carry wrench.
            const float t0 = __shfl_xor_sync(FULL, s0, 16);
            const float t1 = __shfl_xor_sync(FULL, s1, 16);
            float v = (lane < 16) ? (s0 + t0) : (s1 + t1);
            #pragma unroll
            for (int off = 8; off > 0; off >>= 1)
                v += __shfl_xor_sync(FULL, v, off);
            // lane 0 = seal total, lane 16 = wrench total.

            const int p = base + j0 + j;
            if (p < n) {
                if (lane == 0)  out[p]     = v + bsel;
                if (lane == 16) out[n + p] = v + bsel;
            }
        }
    }
}

extern "C" void kernel_launch(void* const* d_in, const int* in_sizes, int n_in,
                              void* d_out, int out_size)
{
    const float* feats = (const float*)d_in[0];      // [150000*256]
    const int*   idx   = (const int*)d_in[1];        // [200000] int32
    const float* w     = (const float*)d_in[2];      // [2*256]
    const float* b     = (const float*)d_in[3];      // [2]
    float* out = (float*)d_out;                      // [2 * n]

    const int n = in_sizes[1];                       // 200000 points

    const int threads = 128;                         // 4 warps/block
    const int warps_needed = (n + 31) / 32;          // 6250
    const int blocks = (warps_needed + 3) / 4;       // 1563
    suction_kernel<<<blocks, threads>>>(feats, idx, w, b, out, n);
}